// round 12
// baseline (speedup 1.0000x reference)
#include <cuda_runtime.h>
#include <cuda_bf16.h>
#include <math.h>
#include <stdint.h>

#define S_DIM 2048
#define X_DIM 2048
#define F_DIM 3072
#define G_DIM 2
#define NKC   48               // 3072 / 64
#define NPART 128              // 16 xblk * 2 g * 4 quarter-cols
#define NFULL 304              // full-tile CTAs (one full wave)
#define NQ    832              // quarter-tile CTAs ((512-304)*4)

#define LDE2   144                     // bytes per smem row (64 bf16 + 8 pad)
#define TILEB  (128 * LDE2)            // 18432 per tile (A or B)
#define STAGEB (2 * TILEB)             // 36864
#define SMEM_TOTAL (3 * STAGEB)        // 110592

// ---- scratch (static, no runtime allocation) ----
__device__ float g_w[G_DIM * F_DIM];
__device__ float g_const[G_DIM];
__device__ float g_R[G_DIM * S_DIM];      // -0.5*A
__device__ float g_Cc[G_DIM * X_DIM];     // -0.5*C
__device__ float g_mp[NPART * S_DIM];
__device__ float g_zp[NPART * S_DIM];
__device__ unsigned g_done[16];           // per-mblk quarter-unit counters (target 128)
__device__ __align__(16) __nv_bfloat16 g_sbuf[(size_t)S_DIM * F_DIM];           // bf16(s)
__device__ __align__(16) __nv_bfloat16 g_xwbuf[(size_t)G_DIM * X_DIM * F_DIM];  // bf16(w*x)

// ---------------------------------------------------------------------------
// PTX helpers (all sm_80-portable)
// ---------------------------------------------------------------------------
__device__ __forceinline__ uint32_t smem_u32(const void* p) {
    uint32_t a;
    asm("{ .reg .u64 t; cvta.to.shared.u64 t, %1; cvt.u32.u64 %0, t; }" : "=r"(a) : "l"(p));
    return a;
}
__device__ __forceinline__ void cp16(uint32_t dst, const void* src) {
    asm volatile("cp.async.cg.shared.global [%0], [%1], 16;" :: "r"(dst), "l"(src) : "memory");
}
#define CP_COMMIT() asm volatile("cp.async.commit_group;" ::: "memory")
#define CP_WAIT1()  asm volatile("cp.async.wait_group 1;" ::: "memory")

__device__ __forceinline__ void ldsm_x4(uint32_t& r0, uint32_t& r1, uint32_t& r2, uint32_t& r3,
                                        uint32_t addr) {
    asm volatile("ldmatrix.sync.aligned.m8n8.x4.shared.b16 {%0,%1,%2,%3}, [%4];"
                 : "=r"(r0), "=r"(r1), "=r"(r2), "=r"(r3) : "r"(addr));
}
__device__ __forceinline__ void mma_bf16(float* c, const uint32_t* a,
                                         uint32_t b0, uint32_t b1) {
    asm volatile("mma.sync.aligned.m16n8k16.row.col.f32.bf16.bf16.f32 "
                 "{%0,%1,%2,%3}, {%4,%5,%6,%7}, {%8,%9}, {%0,%1,%2,%3};"
                 : "+f"(c[0]), "+f"(c[1]), "+f"(c[2]), "+f"(c[3])
                 : "r"(a[0]), "r"(a[1]), "r"(a[2]), "r"(a[3]), "r"(b0), "r"(b1));
}

// ---------------------------------------------------------------------------
// prep 1: w = 1/std^2, const[g]
// ---------------------------------------------------------------------------
__global__ void prep_w_kernel(const float* __restrict__ stdp) {
    const int g = blockIdx.x;
    __shared__ float red[256];
    float acc = 0.f;
    for (int f = threadIdx.x; f < F_DIM; f += 256) {
        float sd = stdp[g * F_DIM + f];
        g_w[g * F_DIM + f] = 1.0f / (sd * sd);
        acc += logf(sd);
    }
    red[threadIdx.x] = acc;
    __syncthreads();
    for (int s = 128; s > 0; s >>= 1) {
        if (threadIdx.x < s) red[threadIdx.x] += red[threadIdx.x + s];
        __syncthreads();
    }
    if (threadIdx.x == 0)
        g_const[g] = -0.5f * (float)F_DIM * logf(6.283185307179586f) - red[0];
}

// ---------------------------------------------------------------------------
// prep 2a: samples row -> bf16(g_sbuf) + g_R[g][row]
// ---------------------------------------------------------------------------
__global__ __launch_bounds__(384)
void prep_s_kernel(const float* __restrict__ samples) {
    const int row  = blockIdx.x;
    const int tid  = threadIdx.x;
    const int lane = tid & 31;
    const int wrp  = tid >> 5;
    const int f0   = tid * 8;
    __shared__ float red0[12], red1[12];

    const float* src = samples + (size_t)row * F_DIM + f0;
    const float4 v0 = *(const float4*)(src);
    const float4 v1 = *(const float4*)(src + 4);
    const float4 w00 = *(const float4*)(g_w + f0);
    const float4 w01 = *(const float4*)(g_w + f0 + 4);
    const float4 w10 = *(const float4*)(g_w + F_DIM + f0);
    const float4 w11 = *(const float4*)(g_w + F_DIM + f0 + 4);

    float p0 = v0.x*v0.x*w00.x + v0.y*v0.y*w00.y + v0.z*v0.z*w00.z + v0.w*v0.w*w00.w
             + v1.x*v1.x*w01.x + v1.y*v1.y*w01.y + v1.z*v1.z*w01.z + v1.w*v1.w*w01.w;
    float p1 = v0.x*v0.x*w10.x + v0.y*v0.y*w10.y + v0.z*v0.z*w10.z + v0.w*v0.w*w10.w
             + v1.x*v1.x*w11.x + v1.y*v1.y*w11.y + v1.z*v1.z*w11.z + v1.w*v1.w*w11.w;

    __nv_bfloat162 p[4];
    p[0] = __float22bfloat162_rn(make_float2(v0.x, v0.y));
    p[1] = __float22bfloat162_rn(make_float2(v0.z, v0.w));
    p[2] = __float22bfloat162_rn(make_float2(v1.x, v1.y));
    p[3] = __float22bfloat162_rn(make_float2(v1.z, v1.w));
    *(uint4*)(g_sbuf + (size_t)row * F_DIM + f0) = *(uint4*)p;

#pragma unroll
    for (int off = 16; off > 0; off >>= 1) {
        p0 += __shfl_xor_sync(0xffffffffu, p0, off);
        p1 += __shfl_xor_sync(0xffffffffu, p1, off);
    }
    if (lane == 0) { red0[wrp] = p0; red1[wrp] = p1; }
    __syncthreads();
    if (tid == 0) {
        float s0 = 0.f, s1 = 0.f;
#pragma unroll
        for (int i = 0; i < 12; i++) { s0 += red0[i]; s1 += red1[i]; }
        g_R[row]         = -0.5f * s0;
        g_R[S_DIM + row] = -0.5f * s1;
    }
}

// ---------------------------------------------------------------------------
// prep 2b: x row -> bf16(w*x) for g=0,1 + g_Cc[g][row]
// ---------------------------------------------------------------------------
__global__ __launch_bounds__(384)
void prep_x_kernel(const float* __restrict__ x) {
    const int row  = blockIdx.x;
    const int tid  = threadIdx.x;
    const int lane = tid & 31;
    const int wrp  = tid >> 5;
    const int f0   = tid * 8;
    __shared__ float red0[12], red1[12];

    const float* src = x + (size_t)row * F_DIM + f0;
    const float4 v0 = *(const float4*)(src);
    const float4 v1 = *(const float4*)(src + 4);
    const float4 w00 = *(const float4*)(g_w + f0);
    const float4 w01 = *(const float4*)(g_w + f0 + 4);
    const float4 w10 = *(const float4*)(g_w + F_DIM + f0);
    const float4 w11 = *(const float4*)(g_w + F_DIM + f0 + 4);

    float p0 = v0.x*v0.x*w00.x + v0.y*v0.y*w00.y + v0.z*v0.z*w00.z + v0.w*v0.w*w00.w
             + v1.x*v1.x*w01.x + v1.y*v1.y*w01.y + v1.z*v1.z*w01.z + v1.w*v1.w*w01.w;
    float p1 = v0.x*v0.x*w10.x + v0.y*v0.y*w10.y + v0.z*v0.z*w10.z + v0.w*v0.w*w10.w
             + v1.x*v1.x*w11.x + v1.y*v1.y*w11.y + v1.z*v1.z*w11.z + v1.w*v1.w*w11.w;

    __nv_bfloat162 p[4];
    p[0] = __float22bfloat162_rn(make_float2(v0.x * w00.x, v0.y * w00.y));
    p[1] = __float22bfloat162_rn(make_float2(v0.z * w00.z, v0.w * w00.w));
    p[2] = __float22bfloat162_rn(make_float2(v1.x * w01.x, v1.y * w01.y));
    p[3] = __float22bfloat162_rn(make_float2(v1.z * w01.z, v1.w * w01.w));
    *(uint4*)(g_xwbuf + (size_t)row * F_DIM + f0) = *(uint4*)p;
    p[0] = __float22bfloat162_rn(make_float2(v0.x * w10.x, v0.y * w10.y));
    p[1] = __float22bfloat162_rn(make_float2(v0.z * w10.z, v0.w * w10.w));
    p[2] = __float22bfloat162_rn(make_float2(v1.x * w11.x, v1.y * w11.y));
    p[3] = __float22bfloat162_rn(make_float2(v1.z * w11.z, v1.w * w11.w));
    *(uint4*)(g_xwbuf + ((size_t)X_DIM + row) * F_DIM + f0) = *(uint4*)p;

#pragma unroll
    for (int off = 16; off > 0; off >>= 1) {
        p0 += __shfl_xor_sync(0xffffffffu, p0, off);
        p1 += __shfl_xor_sync(0xffffffffu, p1, off);
    }
    if (lane == 0) { red0[wrp] = p0; red1[wrp] = p1; }
    __syncthreads();
    if (tid == 0) {
        float s0 = 0.f, s1 = 0.f;
#pragma unroll
        for (int i = 0; i < 12; i++) { s0 += red0[i]; s1 += red1[i]; }
        g_Cc[row]         = -0.5f * s0;
        g_Cc[X_DIM + row] = -0.5f * s1;
    }
}

// ---------------------------------------------------------------------------
// loaders
// ---------------------------------------------------------------------------
__device__ __forceinline__ void issue_chunk_full(uint32_t sbase, int st, int kc,
                                                 const char* Ag, const char* Bg, int tid) {
    const int r = tid >> 3;
    const int c = (tid & 7) * 16;
    const uint32_t aT = sbase + (uint32_t)st * STAGEB;
    const uint32_t bT = aT + TILEB;
    const size_t gstep = (size_t)32 * (F_DIM * 2);
    const size_t go = (size_t)r * (F_DIM * 2) + (size_t)kc * 128 + (size_t)c;
    const uint32_t so = (uint32_t)r * LDE2 + (uint32_t)c;
#pragma unroll
    for (int i = 0; i < 4; i++) {
        cp16(aT + so + (uint32_t)i * 32 * LDE2, Ag + go + (size_t)i * gstep);
        cp16(bT + so + (uint32_t)i * 32 * LDE2, Bg + go + (size_t)i * gstep);
    }
    CP_COMMIT();
}

__device__ __forceinline__ void issue_chunk_quarter(uint32_t sbase, int st, int kc,
                                                    const char* Ag, const char* Bg, int tid) {
    const int r = tid >> 3;
    const int c = (tid & 7) * 16;
    const uint32_t aT = sbase + (uint32_t)st * STAGEB;
    const uint32_t bT = aT + TILEB;
    const size_t gstep = (size_t)32 * (F_DIM * 2);
    const size_t go = (size_t)r * (F_DIM * 2) + (size_t)kc * 128 + (size_t)c;
    const uint32_t so = (uint32_t)r * LDE2 + (uint32_t)c;
#pragma unroll
    for (int i = 0; i < 4; i++)
        cp16(aT + so + (uint32_t)i * 32 * LDE2, Ag + go + (size_t)i * gstep);
    cp16(bT + so, Bg + go);       // B: 32 rows only
    CP_COMMIT();
}

// ---------------------------------------------------------------------------
// row-LSE + publish: per-lane 8 logits for one row/quarter; shfl over 4 tt lanes
// ---------------------------------------------------------------------------
__device__ __forceinline__ void lse_publish(const float* l8, float Ri, int tt,
                                            int slot, int grow) {
    float m = -INFINITY;
#pragma unroll
    for (int j = 0; j < 8; j++) m = fmaxf(m, l8[j]);
    float z = 0.f;
#pragma unroll
    for (int j = 0; j < 8; j++) z += __expf(l8[j] - m);
#pragma unroll
    for (int off = 1; off < 4; off <<= 1) {
        const float om = __shfl_xor_sync(0xffffffffu, m, off);
        const float oz = __shfl_xor_sync(0xffffffffu, z, off);
        const float nm = fmaxf(m, om);
        z = z * __expf(m - nm) + oz * __expf(om - nm);
        m = nm;
    }
    if (tt == 0) {
        g_mp[(size_t)slot * S_DIM + grow] = m;
        g_zp[(size_t)slot * S_DIM + grow] = z;
    }
    (void)Ri;
}

// ---------------------------------------------------------------------------
// main: bf16 mma.sync GEMM + fused LSE. Long-first ragged grid:
//   bid [0,304):    full tiles 128x128 (logical tiles 0..303)
//   bid [304,1136): quarter tiles 128x32 (logical tiles 304..511, 4 quarters)
// Partials per (g, xblk, quarter-col). Counter finalize at 128 units per mblk.
// ---------------------------------------------------------------------------
__global__ __launch_bounds__(256, 2)
void gemm_lse_mma_kernel(float* __restrict__ out) {
    extern __shared__ __align__(1024) char smem[];
    const uint32_t sbase = smem_u32(smem);

    const int tid  = threadIdx.x;
    const int wid  = tid >> 5;
    const int lane = tid & 31;
    const int tg   = lane >> 2;
    const int tt   = lane & 3;
    const int bgrp = lane >> 3;

    const int bid = blockIdx.x;
    const bool full = (bid < NFULL);
    int lt, quarter;
    if (full) { lt = bid; quarter = 0; }
    else { const int q = bid - NFULL; lt = NFULL + (q >> 2); quarter = q & 3; }
    const int mblk = lt >> 5;
    const int r5   = lt & 31;
    const int xblk = r5 >> 1;
    const int g    = r5 & 1;
    const int m0   = mblk * 128;

    unsigned myunits;

    if (full) {
        const int x0 = xblk * 128;
        const int wr = wid >> 2;   // 0..1
        const int wc = wid & 3;    // 0..3
        const char* Ag = (const char*)(g_sbuf  + (size_t)m0 * F_DIM);
        const char* Bg = (const char*)(g_xwbuf + ((size_t)g * X_DIM + x0) * F_DIM);

        float acc[4][4][4];
#pragma unroll
        for (int mt = 0; mt < 4; mt++)
#pragma unroll
            for (int nt = 0; nt < 4; nt++)
#pragma unroll
                for (int j = 0; j < 4; j++) acc[mt][nt][j] = 0.f;

        issue_chunk_full(sbase, 0, 0, Ag, Bg, tid);
        issue_chunk_full(sbase, 1, 1, Ag, Bg, tid);

        const uint32_t aRowOff = (uint32_t)(wr * 64 + (lane & 15)) * LDE2
                               + (uint32_t)((lane >> 4) * 8) * 2;
        const uint32_t bRowOff = (uint32_t)(wc * 32 + ((bgrp >> 1) * 8) + (lane & 7)) * LDE2
                               + (uint32_t)((bgrp & 1) * 8) * 2;

        int st = 0, stn = 2;
#pragma unroll 1
        for (int kc = 0; kc < NKC; kc++) {
            CP_WAIT1();
            __syncthreads();
            if (kc + 2 < NKC)
                issue_chunk_full(sbase, stn, kc + 2, Ag, Bg, tid);

            const uint32_t aT = sbase + (uint32_t)st * STAGEB;
            const uint32_t bT = aT + TILEB;
#pragma unroll
            for (int ks = 0; ks < 4; ks++) {
                const uint32_t kso = (uint32_t)(ks * 32);
                uint32_t b[4][2];
#pragma unroll
                for (int np = 0; np < 2; np++)
                    ldsm_x4(b[2*np][0], b[2*np][1], b[2*np+1][0], b[2*np+1][1],
                            bT + bRowOff + (uint32_t)(np * 16) * LDE2 + kso);
                uint32_t a[4][4];
#pragma unroll
                for (int mt = 0; mt < 4; mt++)
                    ldsm_x4(a[mt][0], a[mt][1], a[mt][2], a[mt][3],
                            aT + aRowOff + (uint32_t)(mt * 16) * LDE2 + kso);
#pragma unroll
                for (int mt = 0; mt < 4; mt++)
#pragma unroll
                    for (int nt = 0; nt < 4; nt++)
                        mma_bf16(acc[mt][nt], a[mt], b[nt][0], b[nt][1]);
            }
            st  = (st  == 2) ? 0 : st  + 1;
            stn = (stn == 2) ? 0 : stn + 1;
        }

        // epilogue: per-warp-col LSE -> slot (g, xblk, wc); no smem combine
        const float cg = g_const[g];
        const int slot = ((g * 16 + xblk) << 2) + wc;
        float Ccj[8];
#pragma unroll
        for (int nt = 0; nt < 4; nt++) {
            Ccj[2*nt+0] = g_Cc[g * X_DIM + x0 + wc * 32 + nt * 8 + tt * 2];
            Ccj[2*nt+1] = g_Cc[g * X_DIM + x0 + wc * 32 + nt * 8 + tt * 2 + 1];
        }
#pragma unroll
        for (int mt = 0; mt < 4; mt++) {
#pragma unroll
            for (int half = 0; half < 2; half++) {
                const int r = wr * 64 + mt * 16 + tg + half * 8;
                const float Ri = g_R[g * S_DIM + m0 + r] + cg;
                float l[8];
#pragma unroll
                for (int j = 0; j < 8; j++)
                    l[j] = acc[mt][j >> 1][half * 2 + (j & 1)] + Ri + Ccj[j];
                lse_publish(l, Ri, tt, slot, m0 + r);
            }
        }
        myunits = 4u;
    } else {
        // ---------------- quarter tile: 128 x 32, 8 warps of 16x32 ----------------
        const int x0 = xblk * 128 + quarter * 32;
        const char* Ag = (const char*)(g_sbuf  + (size_t)m0 * F_DIM);
        const char* Bg = (const char*)(g_xwbuf + ((size_t)g * X_DIM + x0) * F_DIM);

        float acc[4][4];
#pragma unroll
        for (int nt = 0; nt < 4; nt++)
#pragma unroll
            for (int j = 0; j < 4; j++) acc[nt][j] = 0.f;

        issue_chunk_quarter(sbase, 0, 0, Ag, Bg, tid);
        issue_chunk_quarter(sbase, 1, 1, Ag, Bg, tid);

        const uint32_t aRowOff = (uint32_t)(wid * 16 + (lane & 15)) * LDE2
                               + (uint32_t)((lane >> 4) * 8) * 2;
        const uint32_t bRowOff = (uint32_t)(((bgrp >> 1) * 8) + (lane & 7)) * LDE2
                               + (uint32_t)((bgrp & 1) * 8) * 2;

        int st = 0, stn = 2;
#pragma unroll 1
        for (int kc = 0; kc < NKC; kc++) {
            CP_WAIT1();
            __syncthreads();
            if (kc + 2 < NKC)
                issue_chunk_quarter(sbase, stn, kc + 2, Ag, Bg, tid);

            const uint32_t aT = sbase + (uint32_t)st * STAGEB;
            const uint32_t bT = aT + TILEB;
#pragma unroll
            for (int ks = 0; ks < 4; ks++) {
                const uint32_t kso = (uint32_t)(ks * 32);
                uint32_t b[4][2];
#pragma unroll
                for (int np = 0; np < 2; np++)
                    ldsm_x4(b[2*np][0], b[2*np][1], b[2*np+1][0], b[2*np+1][1],
                            bT + bRowOff + (uint32_t)(np * 16) * LDE2 + kso);
                uint32_t a[4];
                ldsm_x4(a[0], a[1], a[2], a[3], aT + aRowOff + kso);
#pragma unroll
                for (int nt = 0; nt < 4; nt++)
                    mma_bf16(acc[nt], a, b[nt][0], b[nt][1]);
            }
            st  = (st  == 2) ? 0 : st  + 1;
            stn = (stn == 2) ? 0 : stn + 1;
        }

        const float cg = g_const[g];
        const int slot = ((g * 16 + xblk) << 2) + quarter;
        float Ccj[8];
#pragma unroll
        for (int nt = 0; nt < 4; nt++) {
            Ccj[2*nt+0] = g_Cc[g * X_DIM + x0 + nt * 8 + tt * 2];
            Ccj[2*nt+1] = g_Cc[g * X_DIM + x0 + nt * 8 + tt * 2 + 1];
        }
#pragma unroll
        for (int half = 0; half < 2; half++) {
            const int r = wid * 16 + tg + half * 8;
            const float Ri = g_R[g * S_DIM + m0 + r] + cg;
            float l[8];
#pragma unroll
            for (int j = 0; j < 8; j++)
                l[j] = acc[j >> 1][half * 2 + (j & 1)] + Ri + Ccj[j];
            lse_publish(l, Ri, tt, slot, m0 + r);
        }
        myunits = 1u;
    }

    // ---------------- race-free inline finalize ----------------
    __shared__ unsigned s_old;
    __threadfence();
    __syncthreads();
    if (tid == 0) s_old = atomicAdd(&g_done[mblk], myunits);
    __syncthreads();
    if (s_old + myunits == 128u) {   // all quarter-units of this mblk published
        __threadfence();
        const int lr = tid >> 1;           // 0..127
        const int r  = m0 + lr;
        const int pb = (tid & 1) * 64;     // split 128 partials across 2 threads
        float m = -INFINITY;
#pragma unroll 8
        for (int p = 0; p < 64; p++)
            m = fmaxf(m, g_mp[(size_t)(pb + p) * S_DIM + r]);
        float Z = 0.f;
#pragma unroll 8
        for (int p = 0; p < 64; p++)
            Z += g_zp[(size_t)(pb + p) * S_DIM + r] * __expf(g_mp[(size_t)(pb + p) * S_DIM + r] - m);
        const float om = __shfl_xor_sync(0xffffffffu, m, 1);
        const float oz = __shfl_xor_sync(0xffffffffu, Z, 1);
        const float nm = fmaxf(m, om);
        Z = Z * __expf(m - nm) + oz * __expf(om - nm);
        if ((tid & 1) == 0)
            out[r] = nm + logf(Z) - logf((float)(X_DIM * G_DIM));
        __syncthreads();
        if (tid == 0) g_done[mblk] = 0;   // reset for next replay
    }
}

// ---------------------------------------------------------------------------
extern "C" void kernel_launch(void* const* d_in, const int* in_sizes, int n_in,
                              void* d_out, int out_size) {
    const float* samples = (const float*)d_in[0];  // [2048, 3072]
    const float* x       = (const float*)d_in[1];  // [2048, 3072]
    const float* stdp    = (const float*)d_in[2];  // [2, 3072]
    float* out = (float*)d_out;                    // [2048]

    cudaFuncSetAttribute(gemm_lse_mma_kernel,
                         cudaFuncAttributeMaxDynamicSharedMemorySize, SMEM_TOTAL);

    prep_w_kernel<<<G_DIM, 256>>>(stdp);        // launch 1
    prep_s_kernel<<<S_DIM, 384>>>(samples);     // launch 2
    prep_x_kernel<<<X_DIM, 384>>>(x);           // launch 3

    gemm_lse_mma_kernel<<<NFULL + NQ, 256, SMEM_TOTAL>>>(out);   // launch 4 (ncu target)
}

// round 13
// speedup vs baseline: 1.1479x; 1.1479x over previous
#include <cuda_runtime.h>
#include <cuda_bf16.h>
#include <math.h>
#include <stdint.h>

#define S_DIM 2048
#define X_DIM 2048
#define F_DIM 3072
#define G_DIM 2
#define NKC   48               // 3072 / 64
#define NPART 32               // 16 x-blocks * 2 gradations
#define NTILES 512
#define NCTA  304              // exactly one 2-CTA/SM wave on 152 SMs

#define LDE2   144                     // bytes per smem row (64 bf16 + 8 pad)
#define TILEB  (128 * LDE2)            // 18432 per tile (A or B)
#define STAGEB (2 * TILEB)             // 36864
#define SMEM_TOTAL (3 * STAGEB)        // 110592
#define SM_RM  (2 * STAGEB)            // epilogue overlay lives in stage 2
#define SM_RZ  (2 * STAGEB + 2048)

// ---- scratch (static, no runtime allocation) ----
__device__ float g_w[G_DIM * F_DIM];
__device__ float g_const[G_DIM];
__device__ float g_R[G_DIM * S_DIM];      // -0.5*A
__device__ float g_Cc[G_DIM * X_DIM];     // -0.5*C
__device__ float g_mp[NPART * S_DIM];
__device__ float g_zp[NPART * S_DIM];
__device__ unsigned g_done[16];           // per-mblk completion counters
__device__ __align__(16) __nv_bfloat16 g_sbuf[(size_t)S_DIM * F_DIM];           // bf16(s)
__device__ __align__(16) __nv_bfloat16 g_xwbuf[(size_t)G_DIM * X_DIM * F_DIM];  // bf16(w*x)

// ---------------------------------------------------------------------------
// PTX helpers (all sm_80-portable)
// ---------------------------------------------------------------------------
__device__ __forceinline__ uint32_t smem_u32(const void* p) {
    uint32_t a;
    asm("{ .reg .u64 t; cvta.to.shared.u64 t, %1; cvt.u32.u64 %0, t; }" : "=r"(a) : "l"(p));
    return a;
}
__device__ __forceinline__ void cp16(uint32_t dst, const void* src) {
    asm volatile("cp.async.cg.shared.global [%0], [%1], 16;" :: "r"(dst), "l"(src) : "memory");
}
#define CP_COMMIT() asm volatile("cp.async.commit_group;" ::: "memory")
#define CP_WAIT1()  asm volatile("cp.async.wait_group 1;" ::: "memory")

__device__ __forceinline__ void ldsm_x4(uint32_t& r0, uint32_t& r1, uint32_t& r2, uint32_t& r3,
                                        uint32_t addr) {
    asm volatile("ldmatrix.sync.aligned.m8n8.x4.shared.b16 {%0,%1,%2,%3}, [%4];"
                 : "=r"(r0), "=r"(r1), "=r"(r2), "=r"(r3) : "r"(addr));
}
__device__ __forceinline__ void mma_bf16(float* c, const uint32_t* a,
                                         uint32_t b0, uint32_t b1) {
    asm volatile("mma.sync.aligned.m16n8k16.row.col.f32.bf16.bf16.f32 "
                 "{%0,%1,%2,%3}, {%4,%5,%6,%7}, {%8,%9}, {%0,%1,%2,%3};"
                 : "+f"(c[0]), "+f"(c[1]), "+f"(c[2]), "+f"(c[3])
                 : "r"(a[0]), "r"(a[1]), "r"(a[2]), "r"(a[3]), "r"(b0), "r"(b1));
}

// ---------------------------------------------------------------------------
// prep 1: w = 1/std^2, const[g]
// ---------------------------------------------------------------------------
__global__ void prep_w_kernel(const float* __restrict__ stdp) {
    const int g = blockIdx.x;
    __shared__ float red[256];
    float acc = 0.f;
    for (int f = threadIdx.x; f < F_DIM; f += 256) {
        float sd = stdp[g * F_DIM + f];
        g_w[g * F_DIM + f] = 1.0f / (sd * sd);
        acc += logf(sd);
    }
    red[threadIdx.x] = acc;
    __syncthreads();
    for (int s = 128; s > 0; s >>= 1) {
        if (threadIdx.x < s) red[threadIdx.x] += red[threadIdx.x + s];
        __syncthreads();
    }
    if (threadIdx.x == 0)
        g_const[g] = -0.5f * (float)F_DIM * logf(6.283185307179586f) - red[0];
}

// ---------------------------------------------------------------------------
// prep 2 (merged): one block per row.
//   blocks [0,2048):    samples row -> bf16(g_sbuf) + g_R[0/1][row]
//   blocks [2048,4096): x row       -> bf16(w*x) g=0,1 + g_Cc[0/1][row]
// ---------------------------------------------------------------------------
__global__ __launch_bounds__(384)
void prep_rows_kernel(const float* __restrict__ samples, const float* __restrict__ x) {
    const int bid  = blockIdx.x;
    const int tid  = threadIdx.x;
    const int lane = tid & 31;
    const int wrp  = tid >> 5;
    const int f0   = tid * 8;
    __shared__ float red0[12], red1[12];

    const int is_x = (bid >= S_DIM);
    const int row  = is_x ? bid - S_DIM : bid;
    const float* src = (is_x ? x : samples) + (size_t)row * F_DIM + f0;

    const float4 v0 = *(const float4*)(src);
    const float4 v1 = *(const float4*)(src + 4);
    const float4 w00 = *(const float4*)(g_w + f0);
    const float4 w01 = *(const float4*)(g_w + f0 + 4);
    const float4 w10 = *(const float4*)(g_w + F_DIM + f0);
    const float4 w11 = *(const float4*)(g_w + F_DIM + f0 + 4);

    float p0 = v0.x*v0.x*w00.x + v0.y*v0.y*w00.y + v0.z*v0.z*w00.z + v0.w*v0.w*w00.w
             + v1.x*v1.x*w01.x + v1.y*v1.y*w01.y + v1.z*v1.z*w01.z + v1.w*v1.w*w01.w;
    float p1 = v0.x*v0.x*w10.x + v0.y*v0.y*w10.y + v0.z*v0.z*w10.z + v0.w*v0.w*w10.w
             + v1.x*v1.x*w11.x + v1.y*v1.y*w11.y + v1.z*v1.z*w11.z + v1.w*v1.w*w11.w;

    if (!is_x) {
        __nv_bfloat162 p[4];
        p[0] = __float22bfloat162_rn(make_float2(v0.x, v0.y));
        p[1] = __float22bfloat162_rn(make_float2(v0.z, v0.w));
        p[2] = __float22bfloat162_rn(make_float2(v1.x, v1.y));
        p[3] = __float22bfloat162_rn(make_float2(v1.z, v1.w));
        *(uint4*)(g_sbuf + (size_t)row * F_DIM + f0) = *(uint4*)p;
    } else {
        __nv_bfloat162 p[4];
        p[0] = __float22bfloat162_rn(make_float2(v0.x * w00.x, v0.y * w00.y));
        p[1] = __float22bfloat162_rn(make_float2(v0.z * w00.z, v0.w * w00.w));
        p[2] = __float22bfloat162_rn(make_float2(v1.x * w01.x, v1.y * w01.y));
        p[3] = __float22bfloat162_rn(make_float2(v1.z * w01.z, v1.w * w01.w));
        *(uint4*)(g_xwbuf + (size_t)row * F_DIM + f0) = *(uint4*)p;
        p[0] = __float22bfloat162_rn(make_float2(v0.x * w10.x, v0.y * w10.y));
        p[1] = __float22bfloat162_rn(make_float2(v0.z * w10.z, v0.w * w10.w));
        p[2] = __float22bfloat162_rn(make_float2(v1.x * w11.x, v1.y * w11.y));
        p[3] = __float22bfloat162_rn(make_float2(v1.z * w11.z, v1.w * w11.w));
        *(uint4*)(g_xwbuf + ((size_t)X_DIM + row) * F_DIM + f0) = *(uint4*)p;
    }

#pragma unroll
    for (int off = 16; off > 0; off >>= 1) {
        p0 += __shfl_xor_sync(0xffffffffu, p0, off);
        p1 += __shfl_xor_sync(0xffffffffu, p1, off);
    }
    if (lane == 0) { red0[wrp] = p0; red1[wrp] = p1; }
    __syncthreads();
    if (tid == 0) {
        float s0 = 0.f, s1 = 0.f;
#pragma unroll
        for (int i = 0; i < 12; i++) { s0 += red0[i]; s1 += red1[i]; }
        float* outp = is_x ? g_Cc : g_R;
        const int n = is_x ? X_DIM : S_DIM;
        outp[row]     = -0.5f * s0;
        outp[n + row] = -0.5f * s1;
    }
}

// ---------------------------------------------------------------------------
// persistent main: bf16 mma.sync GEMM (128x128, BK=64, 3 stages) + fused LSE.
// grid = 304 CTAs; CTA bid runs tiles {bid, bid+304}. The chunk stream is
// continuous across the tile boundary (next tile's chunks 0-1 load during
// this tile's last iterations + epilogue). Stage rotation: chunk j -> j%3;
// 48%3==0, so the epilogue always has stage 2 free for sRm/sRz.
// ---------------------------------------------------------------------------
__device__ __forceinline__ void issue_chunk(uint32_t sbase, int st, int kc,
                                            const char* Ag, const char* Bg, int tid) {
    const int r = tid >> 3;              // 0..31
    const int c = (tid & 7) * 16;        // byte col within 128B row
    const uint32_t aT = sbase + (uint32_t)st * STAGEB;
    const uint32_t bT = aT + TILEB;
    const size_t gstep = (size_t)32 * (F_DIM * 2);
    const size_t go = (size_t)r * (F_DIM * 2) + (size_t)kc * 128 + (size_t)c;
    const uint32_t so = (uint32_t)r * LDE2 + (uint32_t)c;
#pragma unroll
    for (int i = 0; i < 4; i++) {
        cp16(aT + so + (uint32_t)i * 32 * LDE2, Ag + go + (size_t)i * gstep);
        cp16(bT + so + (uint32_t)i * 32 * LDE2, Bg + go + (size_t)i * gstep);
    }
    CP_COMMIT();
}

__global__ __launch_bounds__(256, 2)
void gemm_lse_mma_kernel(float* __restrict__ out) {
    extern __shared__ __align__(1024) char smem[];
    const uint32_t sbase = smem_u32(smem);

    const int tid  = threadIdx.x;
    const int wid  = tid >> 5;
    const int lane = tid & 31;
    const int wr   = wid >> 2;   // 0..1
    const int wc   = wid & 3;    // 0..3
    const int tg   = lane >> 2;  // 0..7
    const int tt   = lane & 3;   // 0..3

    const int ntiles = (blockIdx.x + NCTA < NTILES) ? 2 : 1;

    // per-thread ldmatrix offsets (tile-independent)
    const uint32_t aRowOff = (uint32_t)(wr * 64 + (lane & 15)) * LDE2
                           + (uint32_t)((lane >> 4) * 8) * 2;
    const int bgrp = lane >> 3;
    const uint32_t bRowOff = (uint32_t)(wc * 32 + ((bgrp >> 1) * 8) + (lane & 7)) * LDE2
                           + (uint32_t)((bgrp & 1) * 8) * 2;

    float* sRm = (float*)(smem + SM_RM);
    float* sRz = (float*)(smem + SM_RZ);
    __shared__ unsigned s_old;

#pragma unroll 1
    for (int t = 0; t < ntiles; t++) {
        const int tile = blockIdx.x + t * NCTA;
        const int mblk = tile >> 5;          // /32
        const int r5   = tile & 31;
        const int xblk = r5 >> 1;
        const int g    = r5 & 1;
        const int m0   = mblk * 128;
        const int x0   = xblk * 128;

        const char* Ag = (const char*)(g_sbuf  + (size_t)m0 * F_DIM);
        const char* Bg = (const char*)(g_xwbuf + ((size_t)g * X_DIM + x0) * F_DIM);

        // next tile's pointers (for cross-boundary chunk streaming)
        const char* AgN = Ag;
        const char* BgN = Bg;
        if (t + 1 < ntiles) {
            const int tile2 = tile + NCTA;
            const int mblk2 = tile2 >> 5;
            const int r52   = tile2 & 31;
            AgN = (const char*)(g_sbuf  + (size_t)(mblk2 * 128) * F_DIM);
            BgN = (const char*)(g_xwbuf + ((size_t)(r52 & 1) * X_DIM + (r52 >> 1) * 128) * F_DIM);
        }

        float acc[4][4][4];
#pragma unroll
        for (int mt = 0; mt < 4; mt++)
#pragma unroll
            for (int nt = 0; nt < 4; nt++)
#pragma unroll
                for (int j = 0; j < 4; j++) acc[mt][nt][j] = 0.f;

        if (t == 0) {   // first tile: prime the pipeline (later tiles pre-primed)
            issue_chunk(sbase, 0, 0, Ag, Bg, tid);
            issue_chunk(sbase, 1, 1, Ag, Bg, tid);
        }

#pragma unroll 1
        for (int kc = 0; kc < NKC; kc++) {
            CP_WAIT1();
            __syncthreads();

            // issue chunk kc+2: this tile's if in range, else next tile's 0/1
            if (kc + 2 < NKC) {
                issue_chunk(sbase, (kc + 2) % 3, kc + 2, Ag, Bg, tid);
            } else if (t + 1 < ntiles) {
                issue_chunk(sbase, (kc + 2) % 3, kc + 2 - NKC, AgN, BgN, tid);
            }

            const uint32_t aT = sbase + (uint32_t)(kc % 3) * STAGEB;
            const uint32_t bT = aT + TILEB;

#pragma unroll
            for (int ks = 0; ks < 4; ks++) {
                const uint32_t kso = (uint32_t)(ks * 32);
                uint32_t b[4][2];
#pragma unroll
                for (int np = 0; np < 2; np++)
                    ldsm_x4(b[2*np][0], b[2*np][1], b[2*np+1][0], b[2*np+1][1],
                            bT + bRowOff + (uint32_t)(np * 16) * LDE2 + kso);
                uint32_t a[4][4];
#pragma unroll
                for (int mt = 0; mt < 4; mt++)
                    ldsm_x4(a[mt][0], a[mt][1], a[mt][2], a[mt][3],
                            aT + aRowOff + (uint32_t)(mt * 16) * LDE2 + kso);
#pragma unroll
                for (int mt = 0; mt < 4; mt++)
#pragma unroll
                    for (int nt = 0; nt < 4; nt++)
                        mma_bf16(acc[mt][nt], a[mt], b[nt][0], b[nt][1]);
            }
        }
        __syncthreads();   // stage 2 consumed (chunk 47); only stages 0/1 in flight

        // ---------------- fused LSE epilogue (overlays stage 2) ----------------
        const float cg = g_const[g];
        float Ccj[8];
#pragma unroll
        for (int nt = 0; nt < 4; nt++) {
            Ccj[2*nt+0] = g_Cc[g * X_DIM + x0 + wc * 32 + nt * 8 + tt * 2];
            Ccj[2*nt+1] = g_Cc[g * X_DIM + x0 + wc * 32 + nt * 8 + tt * 2 + 1];
        }
#pragma unroll
        for (int mt = 0; mt < 4; mt++) {
#pragma unroll
            for (int half = 0; half < 2; half++) {
                const int r = wr * 64 + mt * 16 + tg + half * 8;
                const float Ri = g_R[g * S_DIM + m0 + r] + cg;
                float l[8];
                float m = -INFINITY;
#pragma unroll
                for (int j = 0; j < 8; j++) {
                    l[j] = acc[mt][j >> 1][half * 2 + (j & 1)] + Ri + Ccj[j];
                    m = fmaxf(m, l[j]);
                }
                float z = 0.f;
#pragma unroll
                for (int j = 0; j < 8; j++) z += __expf(l[j] - m);
#pragma unroll
                for (int off = 1; off < 4; off <<= 1) {
                    const float om = __shfl_xor_sync(0xffffffffu, m, off);
                    const float oz = __shfl_xor_sync(0xffffffffu, z, off);
                    const float nm = fmaxf(m, om);
                    z = z * __expf(m - nm) + oz * __expf(om - nm);
                    m = nm;
                }
                if (tt == 0) { sRm[r * 4 + wc] = m; sRz[r * 4 + wc] = z; }
            }
        }
        __syncthreads();

        if (tid < 128) {
            float m = -INFINITY;
#pragma unroll
            for (int i = 0; i < 4; i++) m = fmaxf(m, sRm[tid * 4 + i]);
            float z = 0.f;
#pragma unroll
            for (int i = 0; i < 4; i++) z += sRz[tid * 4 + i] * __expf(sRm[tid * 4 + i] - m);
            const int p = g * 16 + xblk;
            g_mp[p * S_DIM + m0 + tid] = m;
            g_zp[p * S_DIM + m0 + tid] = z;
        }

        // ---------------- race-free inline finalize ----------------
        __threadfence();
        __syncthreads();
        if (tid == 0) s_old = atomicAdd(&g_done[mblk], 1u);
        __syncthreads();
        if (s_old == 31u) {
            __threadfence();
            const int lr = tid >> 1;
            const int r  = m0 + lr;
            const int pb = (tid & 1) * 16;
            float m = -INFINITY;
#pragma unroll
            for (int p = 0; p < 16; p++)
                m = fmaxf(m, g_mp[(pb + p) * S_DIM + r]);
            float Z = 0.f;
#pragma unroll
            for (int p = 0; p < 16; p++)
                Z += g_zp[(pb + p) * S_DIM + r] * __expf(g_mp[(pb + p) * S_DIM + r] - m);
            const float om = __shfl_xor_sync(0xffffffffu, m, 1);
            const float oz = __shfl_xor_sync(0xffffffffu, Z, 1);
            const float nm = fmaxf(m, om);
            Z = Z * __expf(m - nm) + oz * __expf(om - nm);
            if ((tid & 1) == 0)
                out[r] = nm + logf(Z) - logf((float)(X_DIM * G_DIM));
            __syncthreads();
            if (tid == 0) g_done[mblk] = 0;   // reset for next replay
        }
        __syncthreads();   // epilogue smem (stage 2) free before next mainloop
    }
}

// ---------------------------------------------------------------------------
extern "C" void kernel_launch(void* const* d_in, const int* in_sizes, int n_in,
                              void* d_out, int out_size) {
    const float* samples = (const float*)d_in[0];  // [2048, 3072]
    const float* x       = (const float*)d_in[1];  // [2048, 3072]
    const float* stdp    = (const float*)d_in[2];  // [2, 3072]
    float* out = (float*)d_out;                    // [2048]

    cudaFuncSetAttribute(gemm_lse_mma_kernel,
                         cudaFuncAttributeMaxDynamicSharedMemorySize, SMEM_TOTAL);

    prep_w_kernel<<<G_DIM, 256>>>(stdp);                    // launch 1
    prep_rows_kernel<<<S_DIM + X_DIM, 384>>>(samples, x);   // launch 2

    gemm_lse_mma_kernel<<<NCTA, 256, SMEM_TOTAL>>>(out);    // launch 3
}

// round 14
// speedup vs baseline: 1.2195x; 1.0624x over previous
#include <cuda_runtime.h>
#include <cuda_bf16.h>
#include <math.h>
#include <stdint.h>

#define S_DIM 2048
#define X_DIM 2048
#define F_DIM 3072
#define G_DIM 2
#define NKC   48               // 3072 / 64
#define NPART 32               // 16 x-blocks * 2 gradations

#define LDE2   144                     // bytes per smem row (64 bf16 + 8 pad)
#define TILEB  (128 * LDE2)            // 18432 per tile (A or B)
#define STAGEB (2 * TILEB)             // 36864
#define SMEM_TOTAL (3 * STAGEB)        // 110592 (epilogue arrays overlay stage 0)

// ---- scratch (static, no runtime allocation) ----
__device__ float g_const[G_DIM];
__device__ float g_R[G_DIM * S_DIM];      // -0.5*A
__device__ float g_Cc[G_DIM * X_DIM];     // -0.5*C
__device__ float g_mp[NPART * S_DIM];
__device__ float g_zp[NPART * S_DIM];
__device__ unsigned g_done[16];           // per-mblk completion counters
__device__ __align__(16) __nv_bfloat16 g_sbuf[(size_t)S_DIM * F_DIM];           // bf16(s)
__device__ __align__(16) __nv_bfloat16 g_xwbuf[(size_t)G_DIM * X_DIM * F_DIM];  // bf16(w*x)

// ---------------------------------------------------------------------------
// PTX helpers (all sm_80-portable)
// ---------------------------------------------------------------------------
__device__ __forceinline__ uint32_t smem_u32(const void* p) {
    uint32_t a;
    asm("{ .reg .u64 t; cvta.to.shared.u64 t, %1; cvt.u32.u64 %0, t; }" : "=r"(a) : "l"(p));
    return a;
}
__device__ __forceinline__ void cp16(uint32_t dst, const void* src) {
    asm volatile("cp.async.cg.shared.global [%0], [%1], 16;" :: "r"(dst), "l"(src) : "memory");
}
#define CP_COMMIT() asm volatile("cp.async.commit_group;" ::: "memory")
#define CP_WAIT1()  asm volatile("cp.async.wait_group 1;" ::: "memory")

__device__ __forceinline__ void ldsm_x4(uint32_t& r0, uint32_t& r1, uint32_t& r2, uint32_t& r3,
                                        uint32_t addr) {
    asm volatile("ldmatrix.sync.aligned.m8n8.x4.shared.b16 {%0,%1,%2,%3}, [%4];"
                 : "=r"(r0), "=r"(r1), "=r"(r2), "=r"(r3) : "r"(addr));
}
__device__ __forceinline__ void mma_bf16(float* c, const uint32_t* a,
                                         uint32_t b0, uint32_t b1) {
    asm volatile("mma.sync.aligned.m16n8k16.row.col.f32.bf16.bf16.f32 "
                 "{%0,%1,%2,%3}, {%4,%5,%6,%7}, {%8,%9}, {%0,%1,%2,%3};"
                 : "+f"(c[0]), "+f"(c[1]), "+f"(c[2]), "+f"(c[3])
                 : "r"(a[0]), "r"(a[1]), "r"(a[2]), "r"(a[3]), "r"(b0), "r"(b1));
}

// ---------------------------------------------------------------------------
// prep (single launch, 4097 blocks of 384):
//   blocks [0,2048):    samples row -> bf16(g_sbuf) + g_R[0/1][row]
//   blocks [2048,4096): x row       -> bf16(w*x) g=0,1 + g_Cc[0/1][row]
//   block 4096:         g_const[g] = -0.5*F*log(2pi) - sum log std
// w = 1/(sd*sd) recomputed inline from stdp (identical fp32 expression
// everywhere -> bit-identical results; stdp is L2-resident).
// ---------------------------------------------------------------------------
__global__ __launch_bounds__(384)
void prep_rows_kernel(const float* __restrict__ samples, const float* __restrict__ x,
                      const float* __restrict__ stdp) {
    const int bid  = blockIdx.x;
    const int tid  = threadIdx.x;
    const int lane = tid & 31;
    const int wrp  = tid >> 5;
    const int f0   = tid * 8;
    __shared__ float red0[12], red1[12];

    if (bid == S_DIM + X_DIM) {
        // const block: sum of log(std) per gradation
        float a0 = 0.f, a1 = 0.f;
#pragma unroll
        for (int i = 0; i < 8; i++) {
            a0 += logf(stdp[f0 + i]);
            a1 += logf(stdp[F_DIM + f0 + i]);
        }
#pragma unroll
        for (int off = 16; off > 0; off >>= 1) {
            a0 += __shfl_xor_sync(0xffffffffu, a0, off);
            a1 += __shfl_xor_sync(0xffffffffu, a1, off);
        }
        if (lane == 0) { red0[wrp] = a0; red1[wrp] = a1; }
        __syncthreads();
        if (tid == 0) {
            float s0 = 0.f, s1 = 0.f;
#pragma unroll
            for (int i = 0; i < 12; i++) { s0 += red0[i]; s1 += red1[i]; }
            const float k = -0.5f * (float)F_DIM * logf(6.283185307179586f);
            g_const[0] = k - s0;
            g_const[1] = k - s1;
        }
        return;
    }

    const int is_x = (bid >= S_DIM);
    const int row  = is_x ? bid - S_DIM : bid;
    const float* src = (is_x ? x : samples) + (size_t)row * F_DIM + f0;

    const float4 v0 = *(const float4*)(src);
    const float4 v1 = *(const float4*)(src + 4);

    // w recomputed inline from stdp
    const float4 sd00 = *(const float4*)(stdp + f0);
    const float4 sd01 = *(const float4*)(stdp + f0 + 4);
    const float4 sd10 = *(const float4*)(stdp + F_DIM + f0);
    const float4 sd11 = *(const float4*)(stdp + F_DIM + f0 + 4);
    float4 w00, w01, w10, w11;
    w00.x = 1.0f / (sd00.x * sd00.x); w00.y = 1.0f / (sd00.y * sd00.y);
    w00.z = 1.0f / (sd00.z * sd00.z); w00.w = 1.0f / (sd00.w * sd00.w);
    w01.x = 1.0f / (sd01.x * sd01.x); w01.y = 1.0f / (sd01.y * sd01.y);
    w01.z = 1.0f / (sd01.z * sd01.z); w01.w = 1.0f / (sd01.w * sd01.w);
    w10.x = 1.0f / (sd10.x * sd10.x); w10.y = 1.0f / (sd10.y * sd10.y);
    w10.z = 1.0f / (sd10.z * sd10.z); w10.w = 1.0f / (sd10.w * sd10.w);
    w11.x = 1.0f / (sd11.x * sd11.x); w11.y = 1.0f / (sd11.y * sd11.y);
    w11.z = 1.0f / (sd11.z * sd11.z); w11.w = 1.0f / (sd11.w * sd11.w);

    float p0 = v0.x*v0.x*w00.x + v0.y*v0.y*w00.y + v0.z*v0.z*w00.z + v0.w*v0.w*w00.w
             + v1.x*v1.x*w01.x + v1.y*v1.y*w01.y + v1.z*v1.z*w01.z + v1.w*v1.w*w01.w;
    float p1 = v0.x*v0.x*w10.x + v0.y*v0.y*w10.y + v0.z*v0.z*w10.z + v0.w*v0.w*w10.w
             + v1.x*v1.x*w11.x + v1.y*v1.y*w11.y + v1.z*v1.z*w11.z + v1.w*v1.w*w11.w;

    if (!is_x) {
        __nv_bfloat162 p[4];
        p[0] = __float22bfloat162_rn(make_float2(v0.x, v0.y));
        p[1] = __float22bfloat162_rn(make_float2(v0.z, v0.w));
        p[2] = __float22bfloat162_rn(make_float2(v1.x, v1.y));
        p[3] = __float22bfloat162_rn(make_float2(v1.z, v1.w));
        *(uint4*)(g_sbuf + (size_t)row * F_DIM + f0) = *(uint4*)p;
    } else {
        __nv_bfloat162 p[4];
        p[0] = __float22bfloat162_rn(make_float2(v0.x * w00.x, v0.y * w00.y));
        p[1] = __float22bfloat162_rn(make_float2(v0.z * w00.z, v0.w * w00.w));
        p[2] = __float22bfloat162_rn(make_float2(v1.x * w01.x, v1.y * w01.y));
        p[3] = __float22bfloat162_rn(make_float2(v1.z * w01.z, v1.w * w01.w));
        *(uint4*)(g_xwbuf + (size_t)row * F_DIM + f0) = *(uint4*)p;
        p[0] = __float22bfloat162_rn(make_float2(v0.x * w10.x, v0.y * w10.y));
        p[1] = __float22bfloat162_rn(make_float2(v0.z * w10.z, v0.w * w10.w));
        p[2] = __float22bfloat162_rn(make_float2(v1.x * w11.x, v1.y * w11.y));
        p[3] = __float22bfloat162_rn(make_float2(v1.z * w11.z, v1.w * w11.w));
        *(uint4*)(g_xwbuf + ((size_t)X_DIM + row) * F_DIM + f0) = *(uint4*)p;
    }

#pragma unroll
    for (int off = 16; off > 0; off >>= 1) {
        p0 += __shfl_xor_sync(0xffffffffu, p0, off);
        p1 += __shfl_xor_sync(0xffffffffu, p1, off);
    }
    if (lane == 0) { red0[wrp] = p0; red1[wrp] = p1; }
    __syncthreads();
    if (tid == 0) {
        float s0 = 0.f, s1 = 0.f;
#pragma unroll
        for (int i = 0; i < 12; i++) { s0 += red0[i]; s1 += red1[i]; }
        float* outp = is_x ? g_Cc : g_R;
        const int n = is_x ? X_DIM : S_DIM;
        outp[row]     = -0.5f * s0;
        outp[n + row] = -0.5f * s1;
    }
}

// ---------------------------------------------------------------------------
// main: bf16 mma.sync GEMM (128x128 tile, BK=64, 3 stages) + fused online LSE
// grid (16, 16, 2) = 512 tiles, 256 threads (8 warps, 2x4), 2 CTA/SM.
// Cross-ks B-fragment double buffering; race-free counter finalize inline.
// (Byte-for-byte the proven 165us GEMM from R9.)
// ---------------------------------------------------------------------------
__device__ __forceinline__ void issue_chunk(uint32_t sbase, int st, int kc,
                                            const char* Ag, const char* Bg, int tid) {
    const int r = tid >> 3;              // 0..31
    const int c = (tid & 7) * 16;        // byte col within 128B row
    const uint32_t aT = sbase + (uint32_t)st * STAGEB;
    const uint32_t bT = aT + TILEB;
    const size_t gstep = (size_t)32 * (F_DIM * 2);
    const size_t go = (size_t)r * (F_DIM * 2) + (size_t)kc * 128 + (size_t)c;
    const uint32_t so = (uint32_t)r * LDE2 + (uint32_t)c;
#pragma unroll
    for (int i = 0; i < 4; i++) {
        cp16(aT + so + (uint32_t)i * 32 * LDE2, Ag + go + (size_t)i * gstep);
        cp16(bT + so + (uint32_t)i * 32 * LDE2, Bg + go + (size_t)i * gstep);
    }
    CP_COMMIT();
}

__global__ __launch_bounds__(256, 2)
void gemm_lse_mma_kernel(float* __restrict__ out) {
    extern __shared__ __align__(1024) char smem[];
    const uint32_t sbase = smem_u32(smem);

    const int tid  = threadIdx.x;
    const int wid  = tid >> 5;
    const int lane = tid & 31;
    const int wr   = wid >> 2;   // 0..1  (64-row band)
    const int wc   = wid & 3;    // 0..3  (32-col band)
    const int tg   = lane >> 2;  // 0..7
    const int tt   = lane & 3;   // 0..3

    const int mblk = blockIdx.x;
    const int xblk = blockIdx.y;
    const int g    = blockIdx.z;
    const int m0   = mblk * 128;
    const int x0   = xblk * 128;

    const char* Ag = (const char*)(g_sbuf  + (size_t)m0 * F_DIM);
    const char* Bg = (const char*)(g_xwbuf + ((size_t)g * X_DIM + x0) * F_DIM);

    float acc[4][4][4];
#pragma unroll
    for (int mt = 0; mt < 4; mt++)
#pragma unroll
        for (int nt = 0; nt < 4; nt++)
#pragma unroll
            for (int j = 0; j < 4; j++) acc[mt][nt][j] = 0.f;

    issue_chunk(sbase, 0, 0, Ag, Bg, tid);
    issue_chunk(sbase, 1, 1, Ag, Bg, tid);

    // per-thread ldmatrix offsets (bytes within tile)
    const uint32_t aRowOff = (uint32_t)(wr * 64 + (lane & 15)) * LDE2
                           + (uint32_t)((lane >> 4) * 8) * 2;
    const int bgrp = lane >> 3;
    const uint32_t bRowOff = (uint32_t)(wc * 32 + ((bgrp >> 1) * 8) + (lane & 7)) * LDE2
                           + (uint32_t)((bgrp & 1) * 8) * 2;

    int st = 0, stn = 2;
#pragma unroll 1
    for (int kc = 0; kc < NKC; kc++) {
        CP_WAIT1();
        __syncthreads();

        if (kc + 2 < NKC)
            issue_chunk(sbase, stn, kc + 2, Ag, Bg, tid);

        const uint32_t aT = sbase + (uint32_t)st * STAGEB;
        const uint32_t bT = aT + TILEB;

        // B fragments double-buffered across ks
        uint32_t bfr[2][8];
        ldsm_x4(bfr[0][0], bfr[0][1], bfr[0][2], bfr[0][3], bT + bRowOff);
        ldsm_x4(bfr[0][4], bfr[0][5], bfr[0][6], bfr[0][7], bT + bRowOff + 16u * LDE2);

#pragma unroll
        for (int ks = 0; ks < 4; ks++) {
            const int cur = ks & 1;
            const int nxt = cur ^ 1;
            if (ks < 3) {
                const uint32_t kso2 = (uint32_t)((ks + 1) * 32);
                ldsm_x4(bfr[nxt][0], bfr[nxt][1], bfr[nxt][2], bfr[nxt][3],
                        bT + bRowOff + kso2);
                ldsm_x4(bfr[nxt][4], bfr[nxt][5], bfr[nxt][6], bfr[nxt][7],
                        bT + bRowOff + 16u * LDE2 + kso2);
            }
            const uint32_t kso = (uint32_t)(ks * 32);
            uint32_t a[4][4];
#pragma unroll
            for (int mt = 0; mt < 4; mt++)
                ldsm_x4(a[mt][0], a[mt][1], a[mt][2], a[mt][3],
                        aT + aRowOff + (uint32_t)(mt * 16) * LDE2 + kso);
#pragma unroll
            for (int mt = 0; mt < 4; mt++)
#pragma unroll
                for (int nt = 0; nt < 4; nt++)
                    mma_bf16(acc[mt][nt], a[mt], bfr[cur][2 * nt], bfr[cur][2 * nt + 1]);
        }
        st  = (st  == 2) ? 0 : st  + 1;
        stn = (stn == 2) ? 0 : stn + 1;
    }
    __syncthreads();   // stages dead; epilogue arrays overlay them

    float* sRm = (float*)(smem);           // 128 rows * 4 warp-cols
    float* sRz = (float*)(smem + 2048);

    // ---------------- fused LSE epilogue ----------------
    const float cg = g_const[g];
    float Ccj[8];
#pragma unroll
    for (int nt = 0; nt < 4; nt++) {
        Ccj[2 * nt + 0] = g_Cc[g * X_DIM + x0 + wc * 32 + nt * 8 + tt * 2];
        Ccj[2 * nt + 1] = g_Cc[g * X_DIM + x0 + wc * 32 + nt * 8 + tt * 2 + 1];
    }
#pragma unroll
    for (int mt = 0; mt < 4; mt++) {
#pragma unroll
        for (int half = 0; half < 2; half++) {
            const int r = wr * 64 + mt * 16 + tg + half * 8;
            const float Ri = g_R[g * S_DIM + m0 + r] + cg;
            float l[8];
            float m = -INFINITY;
#pragma unroll
            for (int j = 0; j < 8; j++) {
                l[j] = acc[mt][j >> 1][half * 2 + (j & 1)] + Ri + Ccj[j];
                m = fmaxf(m, l[j]);
            }
            float z = 0.f;
#pragma unroll
            for (int j = 0; j < 8; j++) z += __expf(l[j] - m);
#pragma unroll
            for (int off = 1; off < 4; off <<= 1) {
                const float om = __shfl_xor_sync(0xffffffffu, m, off);
                const float oz = __shfl_xor_sync(0xffffffffu, z, off);
                const float nm = fmaxf(m, om);
                z = z * __expf(m - nm) + oz * __expf(om - nm);
                m = nm;
            }
            if (tt == 0) { sRm[r * 4 + wc] = m; sRz[r * 4 + wc] = z; }
        }
    }
    __syncthreads();

    if (tid < 128) {
        float m = -INFINITY;
#pragma unroll
        for (int i = 0; i < 4; i++) m = fmaxf(m, sRm[tid * 4 + i]);
        float z = 0.f;
#pragma unroll
        for (int i = 0; i < 4; i++) z += sRz[tid * 4 + i] * __expf(sRm[tid * 4 + i] - m);
        const int p = g * 16 + xblk;
        g_mp[p * S_DIM + m0 + tid] = m;
        g_zp[p * S_DIM + m0 + tid] = z;
    }

    // ---------------- race-free inline finalize ----------------
    __shared__ unsigned s_old;
    __threadfence();
    __syncthreads();
    if (tid == 0) s_old = atomicAdd(&g_done[mblk], 1u);
    __syncthreads();
    if (s_old == 31u) {      // all 32 (xblk, g) tiles of this mblk published
        __threadfence();
        const int lr = tid >> 1;           // 0..127
        const int r  = m0 + lr;
        const int pb = (tid & 1) * 16;     // split 32 partials across 2 threads
        float m = -INFINITY;
#pragma unroll
        for (int p = 0; p < 16; p++)
            m = fmaxf(m, g_mp[(pb + p) * S_DIM + r]);
        float Z = 0.f;
#pragma unroll
        for (int p = 0; p < 16; p++)
            Z += g_zp[(pb + p) * S_DIM + r] * __expf(g_mp[(pb + p) * S_DIM + r] - m);
        const float om = __shfl_xor_sync(0xffffffffu, m, 1);
        const float oz = __shfl_xor_sync(0xffffffffu, Z, 1);
        const float nm = fmaxf(m, om);
        Z = Z * __expf(m - nm) + oz * __expf(om - nm);
        if ((tid & 1) == 0)
            out[r] = nm + logf(Z) - logf((float)(X_DIM * G_DIM));
        __syncthreads();
        if (tid == 0) g_done[mblk] = 0;   // reset for next replay
    }
}

// ---------------------------------------------------------------------------
extern "C" void kernel_launch(void* const* d_in, const int* in_sizes, int n_in,
                              void* d_out, int out_size) {
    const float* samples = (const float*)d_in[0];  // [2048, 3072]
    const float* x       = (const float*)d_in[1];  // [2048, 3072]
    const float* stdp    = (const float*)d_in[2];  // [2, 3072]
    float* out = (float*)d_out;                    // [2048]

    cudaFuncSetAttribute(gemm_lse_mma_kernel,
                         cudaFuncAttributeMaxDynamicSharedMemorySize, SMEM_TOTAL);

    prep_rows_kernel<<<S_DIM + X_DIM + 1, 384>>>(samples, x, stdp);  // launch 1

    dim3 grid(S_DIM / 128, X_DIM / 128, G_DIM);
    gemm_lse_mma_kernel<<<grid, 256, SMEM_TOTAL>>>(out);             // launch 2
}

// round 16
// speedup vs baseline: 1.3131x; 1.0768x over previous
#include <cuda_runtime.h>
#include <cuda_bf16.h>
#include <math.h>
#include <stdint.h>

#define S_DIM 2048
#define X_DIM 2048
#define F_DIM 3072
#define G_DIM 2
#define NKC   48               // 3072 / 64
#define NPART 32               // 16 x-blocks * 2 gradations

#define LDE2   144                     // bytes per smem row (64 bf16 + 8 pad)
#define TILEB  (128 * LDE2)            // 18432 per tile (A or B)
#define STAGEB (2 * TILEB)             // 36864
#define SMEM_MB   (3 * STAGEB)         // mbarriers live past the stages
#define SMEM_TOTAL (SMEM_MB + 64)      // 110656 (epilogue arrays overlay stage 0)

// ---- scratch (static, no runtime allocation) ----
__device__ float g_const[G_DIM];
__device__ float g_R[G_DIM * S_DIM];      // -0.5*A
__device__ float g_Cc[G_DIM * X_DIM];     // -0.5*C
__device__ float g_mp[NPART * S_DIM];
__device__ float g_zp[NPART * S_DIM];
__device__ unsigned g_done[16];           // per-mblk completion counters
__device__ __align__(16) __nv_bfloat16 g_sbuf[(size_t)S_DIM * F_DIM];           // bf16(s)
__device__ __align__(16) __nv_bfloat16 g_xwbuf[(size_t)G_DIM * X_DIM * F_DIM];  // bf16(w*x)

// ---------------------------------------------------------------------------
// PTX helpers (all sm_80-portable; no 'a'-suffix features)
// ---------------------------------------------------------------------------
__device__ __forceinline__ uint32_t smem_u32(const void* p) {
    uint32_t a;
    asm("{ .reg .u64 t; cvta.to.shared.u64 t, %1; cvt.u32.u64 %0, t; }" : "=r"(a) : "l"(p));
    return a;
}
__device__ __forceinline__ void cp16(uint32_t dst, const void* src) {
    asm volatile("cp.async.cg.shared.global [%0], [%1], 16;" :: "r"(dst), "l"(src) : "memory");
}
// arrive on mbarrier when ALL of this thread's prior cp.asyncs have completed.
// .noinc is load-bearing: without it the pending count is pre-incremented and
// the arrive nets to zero, so a barrier fed only by cp-arrives never flips.
__device__ __forceinline__ void cp_async_mbar_arrive(uint32_t mbar) {
    asm volatile("cp.async.mbarrier.arrive.noinc.shared::cta.b64 [%0];" :: "r"(mbar) : "memory");
}
__device__ __forceinline__ void mbar_init(uint32_t a, uint32_t cnt) {
    asm volatile("mbarrier.init.shared.b64 [%0], %1;" :: "r"(a), "r"(cnt) : "memory");
}
__device__ __forceinline__ void mbar_arrive(uint32_t a) {
    asm volatile("mbarrier.arrive.release.cta.shared::cta.b64 _, [%0];" :: "r"(a) : "memory");
}
__device__ __forceinline__ void mbar_wait(uint32_t a, uint32_t parity) {
    asm volatile(
        "{\n\t.reg .pred P;\n"
        "LW_%=:\n\t"
        "mbarrier.try_wait.parity.acquire.cta.shared::cta.b64 P, [%0], %1, 0x989680;\n\t"
        "@P bra.uni LD_%=;\n\t"
        "bra.uni LW_%=;\n\t"
        "LD_%=:\n\t}"
        :: "r"(a), "r"(parity) : "memory");
}
__device__ __forceinline__ void ldsm_x4(uint32_t& r0, uint32_t& r1, uint32_t& r2, uint32_t& r3,
                                        uint32_t addr) {
    asm volatile("ldmatrix.sync.aligned.m8n8.x4.shared.b16 {%0,%1,%2,%3}, [%4];"
                 : "=r"(r0), "=r"(r1), "=r"(r2), "=r"(r3) : "r"(addr));
}
__device__ __forceinline__ void mma_bf16(float* c, const uint32_t* a,
                                         uint32_t b0, uint32_t b1) {
    asm volatile("mma.sync.aligned.m16n8k16.row.col.f32.bf16.bf16.f32 "
                 "{%0,%1,%2,%3}, {%4,%5,%6,%7}, {%8,%9}, {%0,%1,%2,%3};"
                 : "+f"(c[0]), "+f"(c[1]), "+f"(c[2]), "+f"(c[3])
                 : "r"(a[0]), "r"(a[1]), "r"(a[2]), "r"(a[3]), "r"(b0), "r"(b1));
}

// ---------------------------------------------------------------------------
// prep (single launch, 4097 blocks of 384): unchanged from the 183us kernel
// ---------------------------------------------------------------------------
__global__ __launch_bounds__(384)
void prep_rows_kernel(const float* __restrict__ samples, const float* __restrict__ x,
                      const float* __restrict__ stdp) {
    const int bid  = blockIdx.x;
    const int tid  = threadIdx.x;
    const int lane = tid & 31;
    const int wrp  = tid >> 5;
    const int f0   = tid * 8;
    __shared__ float red0[12], red1[12];

    if (bid == S_DIM + X_DIM) {
        float a0 = 0.f, a1 = 0.f;
#pragma unroll
        for (int i = 0; i < 8; i++) {
            a0 += logf(stdp[f0 + i]);
            a1 += logf(stdp[F_DIM + f0 + i]);
        }
#pragma unroll
        for (int off = 16; off > 0; off >>= 1) {
            a0 += __shfl_xor_sync(0xffffffffu, a0, off);
            a1 += __shfl_xor_sync(0xffffffffu, a1, off);
        }
        if (lane == 0) { red0[wrp] = a0; red1[wrp] = a1; }
        __syncthreads();
        if (tid == 0) {
            float s0 = 0.f, s1 = 0.f;
#pragma unroll
            for (int i = 0; i < 12; i++) { s0 += red0[i]; s1 += red1[i]; }
            const float k = -0.5f * (float)F_DIM * logf(6.283185307179586f);
            g_const[0] = k - s0;
            g_const[1] = k - s1;
        }
        return;
    }

    const int is_x = (bid >= S_DIM);
    const int row  = is_x ? bid - S_DIM : bid;
    const float* src = (is_x ? x : samples) + (size_t)row * F_DIM + f0;

    const float4 v0 = *(const float4*)(src);
    const float4 v1 = *(const float4*)(src + 4);

    const float4 sd00 = *(const float4*)(stdp + f0);
    const float4 sd01 = *(const float4*)(stdp + f0 + 4);
    const float4 sd10 = *(const float4*)(stdp + F_DIM + f0);
    const float4 sd11 = *(const float4*)(stdp + F_DIM + f0 + 4);
    float4 w00, w01, w10, w11;
    w00.x = 1.0f / (sd00.x * sd00.x); w00.y = 1.0f / (sd00.y * sd00.y);
    w00.z = 1.0f / (sd00.z * sd00.z); w00.w = 1.0f / (sd00.w * sd00.w);
    w01.x = 1.0f / (sd01.x * sd01.x); w01.y = 1.0f / (sd01.y * sd01.y);
    w01.z = 1.0f / (sd01.z * sd01.z); w01.w = 1.0f / (sd01.w * sd01.w);
    w10.x = 1.0f / (sd10.x * sd10.x); w10.y = 1.0f / (sd10.y * sd10.y);
    w10.z = 1.0f / (sd10.z * sd10.z); w10.w = 1.0f / (sd10.w * sd10.w);
    w11.x = 1.0f / (sd11.x * sd11.x); w11.y = 1.0f / (sd11.y * sd11.y);
    w11.z = 1.0f / (sd11.z * sd11.z); w11.w = 1.0f / (sd11.w * sd11.w);

    float p0 = v0.x*v0.x*w00.x + v0.y*v0.y*w00.y + v0.z*v0.z*w00.z + v0.w*v0.w*w00.w
             + v1.x*v1.x*w01.x + v1.y*v1.y*w01.y + v1.z*v1.z*w01.z + v1.w*v1.w*w01.w;
    float p1 = v0.x*v0.x*w10.x + v0.y*v0.y*w10.y + v0.z*v0.z*w10.z + v0.w*v0.w*w10.w
             + v1.x*v1.x*w11.x + v1.y*v1.y*w11.y + v1.z*v1.z*w11.z + v1.w*v1.w*w11.w;

    if (!is_x) {
        __nv_bfloat162 p[4];
        p[0] = __float22bfloat162_rn(make_float2(v0.x, v0.y));
        p[1] = __float22bfloat162_rn(make_float2(v0.z, v0.w));
        p[2] = __float22bfloat162_rn(make_float2(v1.x, v1.y));
        p[3] = __float22bfloat162_rn(make_float2(v1.z, v1.w));
        *(uint4*)(g_sbuf + (size_t)row * F_DIM + f0) = *(uint4*)p;
    } else {
        __nv_bfloat162 p[4];
        p[0] = __float22bfloat162_rn(make_float2(v0.x * w00.x, v0.y * w00.y));
        p[1] = __float22bfloat162_rn(make_float2(v0.z * w00.z, v0.w * w00.w));
        p[2] = __float22bfloat162_rn(make_float2(v1.x * w01.x, v1.y * w01.y));
        p[3] = __float22bfloat162_rn(make_float2(v1.z * w01.z, v1.w * w01.w));
        *(uint4*)(g_xwbuf + (size_t)row * F_DIM + f0) = *(uint4*)p;
        p[0] = __float22bfloat162_rn(make_float2(v0.x * w10.x, v0.y * w10.y));
        p[1] = __float22bfloat162_rn(make_float2(v0.z * w10.z, v0.w * w10.w));
        p[2] = __float22bfloat162_rn(make_float2(v1.x * w11.x, v1.y * w11.y));
        p[3] = __float22bfloat162_rn(make_float2(v1.z * w11.z, v1.w * w11.w));
        *(uint4*)(g_xwbuf + ((size_t)X_DIM + row) * F_DIM + f0) = *(uint4*)p;
    }

#pragma unroll
    for (int off = 16; off > 0; off >>= 1) {
        p0 += __shfl_xor_sync(0xffffffffu, p0, off);
        p1 += __shfl_xor_sync(0xffffffffu, p1, off);
    }
    if (lane == 0) { red0[wrp] = p0; red1[wrp] = p1; }
    __syncthreads();
    if (tid == 0) {
        float s0 = 0.f, s1 = 0.f;
#pragma unroll
        for (int i = 0; i < 12; i++) { s0 += red0[i]; s1 += red1[i]; }
        float* outp = is_x ? g_Cc : g_R;
        const int n = is_x ? X_DIM : S_DIM;
        outp[row]     = -0.5f * s0;
        outp[n + row] = -0.5f * s1;
    }
}

// ---------------------------------------------------------------------------
// main: bf16 mma.sync GEMM (128x128, BK=64, 3 stages) + fused online LSE.
// mbarrier producer/consumer pipeline (cuda::pipeline pattern, .noinc) replaces
// the per-chunk __syncthreads: warps desynchronize, spreading the post-barrier
// LDSM convoy across the chunk period.
// ---------------------------------------------------------------------------
__device__ __forceinline__ void issue_chunk(uint32_t sbase, int st, int kc,
                                            const char* Ag, const char* Bg, int tid) {
    const int r = tid >> 3;              // 0..31
    const int c = (tid & 7) * 16;        // byte col within 128B row
    const uint32_t aT = sbase + (uint32_t)st * STAGEB;
    const uint32_t bT = aT + TILEB;
    const size_t gstep = (size_t)32 * (F_DIM * 2);
    const size_t go = (size_t)r * (F_DIM * 2) + (size_t)kc * 128 + (size_t)c;
    const uint32_t so = (uint32_t)r * LDE2 + (uint32_t)c;
#pragma unroll
    for (int i = 0; i < 4; i++) {
        cp16(aT + so + (uint32_t)i * 32 * LDE2, Ag + go + (size_t)i * gstep);
        cp16(bT + so + (uint32_t)i * 32 * LDE2, Bg + go + (size_t)i * gstep);
    }
}

__global__ __launch_bounds__(256, 2)
void gemm_lse_mma_kernel(float* __restrict__ out) {
    extern __shared__ __align__(1024) char smem[];
    const uint32_t sbase = smem_u32(smem);

    const int tid  = threadIdx.x;
    const int wid  = tid >> 5;
    const int lane = tid & 31;
    const int wr   = wid >> 2;   // 0..1  (64-row band)
    const int wc   = wid & 3;    // 0..3  (32-col band)
    const int tg   = lane >> 2;  // 0..7
    const int tt   = lane & 3;   // 0..3

    const int mblk = blockIdx.x;
    const int xblk = blockIdx.y;
    const int g    = blockIdx.z;
    const int m0   = mblk * 128;
    const int x0   = xblk * 128;

    const char* Ag = (const char*)(g_sbuf  + (size_t)m0 * F_DIM);
    const char* Bg = (const char*)(g_xwbuf + ((size_t)g * X_DIM + x0) * F_DIM);

    // mbarriers: full[s] at SMEM_MB + s*16, empty[s] at +8
    const uint32_t mbF0 = sbase + SMEM_MB;
#define MB_FULL(s)  (mbF0 + (uint32_t)(s) * 16u)
#define MB_EMPTY(s) (mbF0 + (uint32_t)(s) * 16u + 8u)

    if (tid == 0) {
#pragma unroll
        for (int s = 0; s < 3; s++) {
            mbar_init(MB_FULL(s), 256);
            mbar_init(MB_EMPTY(s), 256);
        }
    }
    __syncthreads();

    float acc[4][4][4];
#pragma unroll
    for (int mt = 0; mt < 4; mt++)
#pragma unroll
        for (int nt = 0; nt < 4; nt++)
#pragma unroll
            for (int j = 0; j < 4; j++) acc[mt][nt][j] = 0.f;

    // prologue: chunks 0,1,2 into stages 0,1,2 (no empty wait on first use)
#pragma unroll
    for (int c0 = 0; c0 < 3; c0++) {
        issue_chunk(sbase, c0, c0, Ag, Bg, tid);
        cp_async_mbar_arrive(MB_FULL(c0));
    }

    // per-thread ldmatrix offsets (bytes within tile)
    const uint32_t aRowOff = (uint32_t)(wr * 64 + (lane & 15)) * LDE2
                           + (uint32_t)((lane >> 4) * 8) * 2;
    const int bgrp = lane >> 3;
    const uint32_t bRowOff = (uint32_t)(wc * 32 + ((bgrp >> 1) * 8) + (lane & 7)) * LDE2
                           + (uint32_t)((bgrp & 1) * 8) * 2;

    int st = 0;
    uint32_t par = 0;   // = (kc/3) & 1
#pragma unroll 1
    for (int kc = 0; kc < NKC; kc++) {
        mbar_wait(MB_FULL(st), par);     // acquire: stage st data visible

        const uint32_t aT = sbase + (uint32_t)st * STAGEB;
        const uint32_t bT = aT + TILEB;

        // B fragments double-buffered across ks
        uint32_t bfr[2][8];
        ldsm_x4(bfr[0][0], bfr[0][1], bfr[0][2], bfr[0][3], bT + bRowOff);
        ldsm_x4(bfr[0][4], bfr[0][5], bfr[0][6], bfr[0][7], bT + bRowOff + 16u * LDE2);

#pragma unroll
        for (int ks = 0; ks < 4; ks++) {
            const int cur = ks & 1;
            const int nxt = cur ^ 1;
            if (ks < 3) {
                const uint32_t kso2 = (uint32_t)((ks + 1) * 32);
                ldsm_x4(bfr[nxt][0], bfr[nxt][1], bfr[nxt][2], bfr[nxt][3],
                        bT + bRowOff + kso2);
                ldsm_x4(bfr[nxt][4], bfr[nxt][5], bfr[nxt][6], bfr[nxt][7],
                        bT + bRowOff + 16u * LDE2 + kso2);
            }
            const uint32_t kso = (uint32_t)(ks * 32);
            uint32_t a[4][4];
#pragma unroll
            for (int mt = 0; mt < 4; mt++)
                ldsm_x4(a[mt][0], a[mt][1], a[mt][2], a[mt][3],
                        aT + aRowOff + (uint32_t)(mt * 16) * LDE2 + kso);
#pragma unroll
            for (int mt = 0; mt < 4; mt++)
#pragma unroll
                for (int nt = 0; nt < 4; nt++)
                    mma_bf16(acc[mt][nt], a[mt], bfr[cur][2 * nt], bfr[cur][2 * nt + 1]);
        }

        mbar_arrive(MB_EMPTY(st));       // release: this thread done reading st

        if (kc + 3 < NKC) {
            // refill stage st with chunk kc+3 once ALL threads consumed chunk kc
            mbar_wait(MB_EMPTY(st), par);
            issue_chunk(sbase, st, kc + 3, Ag, Bg, tid);
            cp_async_mbar_arrive(MB_FULL(st));
        }

        if (st == 2) { st = 0; par ^= 1; } else st++;
    }
    __syncthreads();   // all consumes done; stages dead -> overlay epilogue

    float* sRm = (float*)(smem);           // 128 rows * 4 warp-cols
    float* sRz = (float*)(smem + 2048);

    // ---------------- fused LSE epilogue ----------------
    const float cg = g_const[g];
    float Ccj[8];
#pragma unroll
    for (int nt = 0; nt < 4; nt++) {
        Ccj[2 * nt + 0] = g_Cc[g * X_DIM + x0 + wc * 32 + nt * 8 + tt * 2];
        Ccj[2 * nt + 1] = g_Cc[g * X_DIM + x0 + wc * 32 + nt * 8 + tt * 2 + 1];
    }
#pragma unroll
    for (int mt = 0; mt < 4; mt++) {
#pragma unroll
        for (int half = 0; half < 2; half++) {
            const int r = wr * 64 + mt * 16 + tg + half * 8;
            const float Ri = g_R[g * S_DIM + m0 + r] + cg;
            float l[8];
            float m = -INFINITY;
#pragma unroll
            for (int j = 0; j < 8; j++) {
                l[j] = acc[mt][j >> 1][half * 2 + (j & 1)] + Ri + Ccj[j];
                m = fmaxf(m, l[j]);
            }
            float z = 0.f;
#pragma unroll
            for (int j = 0; j < 8; j++) z += __expf(l[j] - m);
#pragma unroll
            for (int off = 1; off < 4; off <<= 1) {
                const float om = __shfl_xor_sync(0xffffffffu, m, off);
                const float oz = __shfl_xor_sync(0xffffffffu, z, off);
                const float nm = fmaxf(m, om);
                z = z * __expf(m - nm) + oz * __expf(om - nm);
                m = nm;
            }
            if (tt == 0) { sRm[r * 4 + wc] = m; sRz[r * 4 + wc] = z; }
        }
    }
    __syncthreads();

    if (tid < 128) {
        float m = -INFINITY;
#pragma unroll
        for (int i = 0; i < 4; i++) m = fmaxf(m, sRm[tid * 4 + i]);
        float z = 0.f;
#pragma unroll
        for (int i = 0; i < 4; i++) z += sRz[tid * 4 + i] * __expf(sRm[tid * 4 + i] - m);
        const int p = g * 16 + xblk;
        g_mp[p * S_DIM + m0 + tid] = m;
        g_zp[p * S_DIM + m0 + tid] = z;
    }

    // ---------------- race-free inline finalize ----------------
    __shared__ unsigned s_old;
    __threadfence();
    __syncthreads();
    if (tid == 0) s_old = atomicAdd(&g_done[mblk], 1u);
    __syncthreads();
    if (s_old == 31u) {      // all 32 (xblk, g) tiles of this mblk published
        __threadfence();
        const int lr = tid >> 1;           // 0..127
        const int r  = m0 + lr;
        const int pb = (tid & 1) * 16;     // split 32 partials across 2 threads
        float m = -INFINITY;
#pragma unroll
        for (int p = 0; p < 16; p++)
            m = fmaxf(m, g_mp[(pb + p) * S_DIM + r]);
        float Z = 0.f;
#pragma unroll
        for (int p = 0; p < 16; p++)
            Z += g_zp[(pb + p) * S_DIM + r] * __expf(g_mp[(pb + p) * S_DIM + r] - m);
        const float om = __shfl_xor_sync(0xffffffffu, m, 1);
        const float oz = __shfl_xor_sync(0xffffffffu, Z, 1);
        const float nm = fmaxf(m, om);
        Z = Z * __expf(m - nm) + oz * __expf(om - nm);
        if ((tid & 1) == 0)
            out[r] = nm + logf(Z) - logf((float)(X_DIM * G_DIM));
        __syncthreads();
        if (tid == 0) g_done[mblk] = 0;   // reset for next replay
    }
}

// ---------------------------------------------------------------------------
extern "C" void kernel_launch(void* const* d_in, const int* in_sizes, int n_in,
                              void* d_out, int out_size) {
    const float* samples = (const float*)d_in[0];  // [2048, 3072]
    const float* x       = (const float*)d_in[1];  // [2048, 3072]
    const float* stdp    = (const float*)d_in[2];  // [2, 3072]
    float* out = (float*)d_out;                    // [2048]

    cudaFuncSetAttribute(gemm_lse_mma_kernel,
                         cudaFuncAttributeMaxDynamicSharedMemorySize, SMEM_TOTAL);

    prep_rows_kernel<<<S_DIM + X_DIM + 1, 384>>>(samples, x, stdp);  // launch 1

    dim3 grid(S_DIM / 128, X_DIM / 128, G_DIM);
    gemm_lse_mma_kernel<<<grid, 256, SMEM_TOTAL>>>(out);             // launch 2
}